// round 16
// baseline (speedup 1.0000x reference)
#include <cuda_runtime.h>

// QLayer analytic form (derivation in R0):
//   Circuit = per-wire RX(x_w) RY(x_w) RZ(theta_w) on |0>, then CNOT ladder
//   0->1 ... 14->15, measure Z everywhere. Heisenberg-picture pullback of Z_w
//   through the ladder gives Z_0 Z_1 ... Z_w on the (product) pre-CNOT state:
//     out[b][w] = prod_{j<=w} cos^2(x[b][j])          (512 x 16)
//
// TERMINAL configuration (measured best across 15 rounds):
//   8192 threads, one per output element, 128 blocks x 64 threads.
//   - 128 SMs in wave-1: widest spread -> smallest drain tail.
//   - 2 warps/SM: one warp's LDG latency covered by the other (1 warp/SM
//     measured ~0.45us slower GPU-side in R6).
//   - __cosf = single MUFU.COS (inputs ~N(0,1); measured rel_err 6.7e-7
//     against the 1e-3 threshold).
//   - 16-lane segmented inclusive prefix product via 4x shfl_up (log-minimal).
//
// Noise characterization (identical binary, 10 runs):
//   GPU 4.42/3.87/3.71/4.00/3.78/4.35/3.97/4.58/4.29/4.26us (mean 4.12);
//   harness bimodal: {4.608 exact} x4 vs {6.85-7.20} x6, mode independent of
//   the GPU-side draw — bimodality lives in the replay/timing layer, not in
//   kernel execution. All pipes <0.2% busy: duration is the launch/ramp
//   floor around ~0.3us of real work. Stationary, source-independent
//   distribution — holding per methodology.

__global__ void __launch_bounds__(64, 1)
qlayer_kernel(const float* __restrict__ x, float* __restrict__ out)
{
    int idx = blockIdx.x * blockDim.x + threadIdx.x;   // 0 .. 8191
    int seg_lane = threadIdx.x & 15;                   // position within 16-wire row

    float cc = __cosf(x[idx]);
    float v = cc * cc;

    // Inclusive prefix product over the 16-lane segment (segments are
    // 16-aligned within each warp).
    #pragma unroll
    for (int off = 1; off < 16; off <<= 1) {
        float o = __shfl_up_sync(0xffffffffu, v, off);
        if (seg_lane >= off) v *= o;
    }

    out[idx] = v;
}

extern "C" void kernel_launch(void* const* d_in, const int* in_sizes, int n_in,
                              void* d_out, int out_size)
{
    const float* x = (const float*)d_in[0];
    // d_in[1] = params (RZ angles): diagonal gates, analytically irrelevant to <Z>.
    float* out = (float*)d_out;

    qlayer_kernel<<<128, 64>>>(x, out);
}

// round 17
// speedup vs baseline: 1.0141x; 1.0141x over previous
#include <cuda_runtime.h>

// QLayer analytic form (derivation in R0):
//   Circuit = per-wire RX(x_w) RY(x_w) RZ(theta_w) on |0>, then CNOT ladder
//   0->1 ... 14->15, measure Z everywhere. Heisenberg-picture pullback of Z_w
//   through the ladder gives Z_0 Z_1 ... Z_w on the (product) pre-CNOT state:
//     out[b][w] = prod_{j<=w} cos^2(x[b][j])          (512 x 16)
//
// TERMINAL configuration (measured best across 16 rounds):
//   8192 threads, one per output element, 128 blocks x 64 threads.
//   - 128 SMs in wave-1: widest spread -> smallest drain tail.
//   - 2 warps/SM: one warp's LDG latency covered by the other (1 warp/SM
//     measured ~0.45us slower GPU-side in R6).
//   - __cosf = single MUFU.COS (inputs ~N(0,1); measured rel_err 6.7e-7
//     against the 1e-3 threshold).
//   - 16-lane segmented inclusive prefix product via 4x shfl_up (log-minimal).
//
// Noise characterization (identical binary, 11 runs):
//   GPU 4.42/3.87/3.71/4.00/3.78/4.35/3.97/4.58/4.29/4.26/4.03us (mean 4.11);
//   harness bimodal: {4.608 exact} x5 vs {6.85-7.20} x6, mode independent of
//   the GPU-side draw. 4.608 is the quantized launch floor for this
//   graph-replay path — unreachable lower by any kernel. All pipes <0.2%
//   busy: duration is launch/ramp envelope around ~0.3us of real work.
//   Stationary, source-independent distribution — holding per methodology.

__global__ void __launch_bounds__(64, 1)
qlayer_kernel(const float* __restrict__ x, float* __restrict__ out)
{
    int idx = blockIdx.x * blockDim.x + threadIdx.x;   // 0 .. 8191
    int seg_lane = threadIdx.x & 15;                   // position within 16-wire row

    float cc = __cosf(x[idx]);
    float v = cc * cc;

    // Inclusive prefix product over the 16-lane segment (segments are
    // 16-aligned within each warp).
    #pragma unroll
    for (int off = 1; off < 16; off <<= 1) {
        float o = __shfl_up_sync(0xffffffffu, v, off);
        if (seg_lane >= off) v *= o;
    }

    out[idx] = v;
}

extern "C" void kernel_launch(void* const* d_in, const int* in_sizes, int n_in,
                              void* d_out, int out_size)
{
    const float* x = (const float*)d_in[0];
    // d_in[1] = params (RZ angles): diagonal gates, analytically irrelevant to <Z>.
    float* out = (float*)d_out;

    qlayer_kernel<<<128, 64>>>(x, out);
}